// round 2
// baseline (speedup 1.0000x reference)
#include <cuda_runtime.h>
#include <math.h>

#define BN 2
#define HH 256
#define WWD 256
#define CC 64
#define PIXB (HH*WWD)          // 65536 pixels per batch
#define NPIX (BN*PIXB)         // 131072
#define NCHUNK 512             // gram chunks of 256 pixels (256 per batch)

// ---------------- device scratch (no allocations allowed) ----------------
__device__ float g_v [NPIX*CC];
__device__ float g_m1[NPIX*CC];
__device__ float g_m2[NPIX*CC];
__device__ float g_t1[NPIX*CC];
__device__ float g_gpart[NCHUNK*4096];
__device__ float g_gram [BN*4096];
__device__ float g_wfold[BN*4096];

__device__ __forceinline__ float dot4(float4 a, float4 b) {
    return a.x*b.x + a.y*b.y + a.z*b.z + a.w*b.w;
}
__device__ __forceinline__ float sigmf(float x) {
    return 1.0f / (1.0f + __expf(-x));
}
__device__ __forceinline__ float geluf(float v) {
    return 0.5f * v * (1.0f + erff(v * 0.70710678118654752f));
}

// ---------------- Gram partials: G_b = sum_n x x^T ----------------
__global__ __launch_bounds__(256) void k_gram_part(const float* __restrict__ x)
{
    __shared__ float sx[8][64];
    int chunk = blockIdx.x;
    int base  = chunk * 256;
    int tid = threadIdx.x;
    int ti = tid >> 4, tj = tid & 15;
    float a00=0,a01=0,a02=0,a03=0, a10=0,a11=0,a12=0,a13=0;
    float a20=0,a21=0,a22=0,a23=0, a30=0,a31=0,a32=0,a33=0;

    for (int pp = 0; pp < 256; pp += 8) {
        __syncthreads();
        int idx = tid * 2;
        int pr = idx >> 6, cc = idx & 63;
        float2 v2 = *(const float2*)&x[(size_t)(base + pp + pr)*CC + cc];
        sx[pr][cc] = v2.x; sx[pr][cc+1] = v2.y;
        __syncthreads();
        #pragma unroll
        for (int p = 0; p < 8; p++) {
            float4 xi = *(const float4*)&sx[p][4*ti];
            float4 xj = *(const float4*)&sx[p][4*tj];
            a00 += xi.x*xj.x; a01 += xi.x*xj.y; a02 += xi.x*xj.z; a03 += xi.x*xj.w;
            a10 += xi.y*xj.x; a11 += xi.y*xj.y; a12 += xi.y*xj.z; a13 += xi.y*xj.w;
            a20 += xi.z*xj.x; a21 += xi.z*xj.y; a22 += xi.z*xj.z; a23 += xi.z*xj.w;
            a30 += xi.w*xj.x; a31 += xi.w*xj.y; a32 += xi.w*xj.z; a33 += xi.w*xj.w;
        }
    }
    float* dst = &g_gpart[(size_t)chunk*4096];
    int r = 4*ti, c = 4*tj;
    dst[(r+0)*64+c+0]=a00; dst[(r+0)*64+c+1]=a01; dst[(r+0)*64+c+2]=a02; dst[(r+0)*64+c+3]=a03;
    dst[(r+1)*64+c+0]=a10; dst[(r+1)*64+c+1]=a11; dst[(r+1)*64+c+2]=a12; dst[(r+1)*64+c+3]=a13;
    dst[(r+2)*64+c+0]=a20; dst[(r+2)*64+c+1]=a21; dst[(r+2)*64+c+2]=a22; dst[(r+2)*64+c+3]=a23;
    dst[(r+3)*64+c+0]=a30; dst[(r+3)*64+c+1]=a31; dst[(r+3)*64+c+2]=a32; dst[(r+3)*64+c+3]=a33;
}

__global__ void k_gram_reduce()
{
    int e = blockIdx.x*blockDim.x + threadIdx.x;
    if (e >= BN*4096) return;
    int b = e >> 12, i = e & 4095;
    float s = 0.f;
    for (int c = 0; c < NCHUNK/BN; c++)
        s += g_gpart[(size_t)(b*(NCHUNK/BN)+c)*4096 + i];
    g_gram[e] = s;
}

// ---------------- tiny solve: attn from Gram, fold Wp*A -> g_wfold ----------------
// one block per batch, norms parallelized
__global__ __launch_bounds__(256) void k_small2(const float* __restrict__ Wq,
                                                const float* __restrict__ Wk,
                                                const float* __restrict__ Wp,
                                                const float* __restrict__ rs)
{
    __shared__ float sG[4096];
    __shared__ float sGq[4096];   // sGq[c*64+o] = (G Wq^T)[c][o]
    __shared__ float sLog[1024];  // [h*256 + d*16 + e]
    __shared__ float sNq[64], sNk[64];
    __shared__ float sPart[256];
    int b = blockIdx.x;
    int tid = threadIdx.x;

    for (int t = tid; t < 4096; t += 256) sG[t] = g_gram[b*4096 + t];
    __syncthreads();
    for (int t = tid; t < 4096; t += 256) {
        int c = t >> 6, o = t & 63;
        float s = 0.f;
        #pragma unroll 8
        for (int i = 0; i < 64; i++) s += sG[c*64+i] * Wq[o*64+i];
        sGq[t] = s;
    }
    __syncthreads();
    // kk partials: 4 threads per output o, each 16 c's
    {
        int o = tid >> 2, part = tid & 3;
        float kp = 0.f;
        for (int c = part*16; c < part*16 + 16; c++) {
            float gk = 0.f;
            #pragma unroll 8
            for (int i = 0; i < 64; i++) gk += sG[c*64+i] * Wk[o*64+i];
            kp += Wk[o*64+c] * gk;
        }
        sPart[tid] = kp;
    }
    __syncthreads();
    if (tid < 64) {
        int o = tid;
        float qq = 0.f;
        #pragma unroll 8
        for (int c = 0; c < 64; c++) qq += Wq[o*64+c] * sGq[c*64+o];
        sNq[o] = fmaxf(sqrtf(fmaxf(qq, 0.f)), 1e-12f);
        float kk = sPart[4*o] + sPart[4*o+1] + sPart[4*o+2] + sPart[4*o+3];
        sNk[o] = fmaxf(sqrtf(fmaxf(kk, 0.f)), 1e-12f);
    }
    __syncthreads();
    for (int t = tid; t < 1024; t += 256) {
        int h = t >> 8, d = (t >> 4) & 15, e = t & 15;
        int rk = h*16 + d, rq = h*16 + e;
        float s = 0.f;
        #pragma unroll 8
        for (int c = 0; c < 64; c++) s += Wk[rk*64+c] * sGq[c*64+rq];
        sLog[t] = s / (sNk[rk] * sNq[rq]) * rs[h];
    }
    __syncthreads();
    if (tid < 64) {
        float* row = &sLog[tid*16];
        float m = row[0];
        for (int e = 1; e < 16; e++) m = fmaxf(m, row[e]);
        float sum = 0.f;
        for (int e = 0; e < 16; e++) { float ev = expf(row[e]-m); row[e] = ev; sum += ev; }
        float inv = 1.f / sum;
        for (int e = 0; e < 16; e++) row[e] *= inv;
    }
    __syncthreads();
    for (int t = tid; t < 4096; t += 256) {
        int o = t >> 6, j = t & 63, hj = j >> 4, ej = j & 15;
        float s = 0.f;
        #pragma unroll
        for (int d = 0; d < 16; d++)
            s += Wp[o*64 + hj*16 + d] * sLog[(hj*16 + d)*16 + ej];
        g_wfold[b*4096 + t] = s;
    }
}

// ---------------- generic per-pixel 64x64 matvec (2 pixels/thread) ----------------
__global__ __launch_bounds__(128) void k_matvec(const float* __restrict__ in,
                                                const float* __restrict__ W,
                                                const float* __restrict__ bias,
                                                float* __restrict__ out)
{
    __shared__ float4 sW[CC*16];
    __shared__ float  sB[CC];
    for (int t = threadIdx.x; t < CC*16; t += blockDim.x) sW[t] = ((const float4*)W)[t];
    for (int t = threadIdx.x; t < CC; t += blockDim.x) sB[t] = bias ? bias[t] : 0.f;
    __syncthreads();

    int p0 = (blockIdx.x * blockDim.x + threadIdx.x) * 2;
    if (p0 >= NPIX) return;
    const float4* in4 = (const float4*)in;
    float4 x0[16], x1[16];
    #pragma unroll
    for (int i = 0; i < 16; i++) x0[i] = in4[(size_t)p0*16 + i];
    #pragma unroll
    for (int i = 0; i < 16; i++) x1[i] = in4[(size_t)(p0+1)*16 + i];

    float4* out4 = (float4*)out;
    for (int g = 0; g < 16; g++) {
        float4 a0, a1;
        a0.x = sB[4*g]; a0.y = sB[4*g+1]; a0.z = sB[4*g+2]; a0.w = sB[4*g+3];
        a1 = a0;
        #pragma unroll
        for (int i = 0; i < 16; i++) {
            float4 w0 = sW[(g*4+0)*16+i];
            float4 w1 = sW[(g*4+1)*16+i];
            float4 w2 = sW[(g*4+2)*16+i];
            float4 w3 = sW[(g*4+3)*16+i];
            a0.x += dot4(w0,x0[i]); a0.y += dot4(w1,x0[i]); a0.z += dot4(w2,x0[i]); a0.w += dot4(w3,x0[i]);
            a1.x += dot4(w0,x1[i]); a1.y += dot4(w1,x1[i]); a1.z += dot4(w2,x1[i]); a1.w += dot4(w3,x1[i]);
        }
        out4[(size_t)p0*16 + g] = a0;
        out4[(size_t)(p0+1)*16 + g] = a1;
    }
}

// ---------------- fused x path: v = Wv*x ; t1 = gelu(dw3x3(x, pe_w1)) ----------------
__global__ __launch_bounds__(128) void k_xv(const float* __restrict__ x,
                                            const float* __restrict__ Wv,
                                            const float* __restrict__ pw1)
{
    __shared__ float4 sW[CC*16];
    __shared__ float  sw1[9*CC];
    for (int t = threadIdx.x; t < CC*16; t += 128) sW[t] = ((const float4*)Wv)[t];
    for (int t = threadIdx.x; t < 9*CC; t += 128) { int c = t/9, k = t%9; sw1[k*CC+c] = pw1[c*9+k]; }
    __syncthreads();

    int p0 = blockIdx.x*256 + threadIdx.x*2;
    const float4* x4 = (const float4*)x;
    float4 x0[16], x1[16];
    #pragma unroll
    for (int i = 0; i < 16; i++) x0[i] = x4[(size_t)p0*16 + i];
    #pragma unroll
    for (int i = 0; i < 16; i++) x1[i] = x4[(size_t)(p0+1)*16 + i];

    // v matvec
    float4* v4 = (float4*)g_v;
    for (int g = 0; g < 16; g++) {
        float4 a0, a1;
        a0.x=0; a0.y=0; a0.z=0; a0.w=0; a1 = a0;
        #pragma unroll
        for (int i = 0; i < 16; i++) {
            float4 w0 = sW[(g*4+0)*16+i];
            float4 w1 = sW[(g*4+1)*16+i];
            float4 w2 = sW[(g*4+2)*16+i];
            float4 w3 = sW[(g*4+3)*16+i];
            a0.x += dot4(w0,x0[i]); a0.y += dot4(w1,x0[i]); a0.z += dot4(w2,x0[i]); a0.w += dot4(w3,x0[i]);
            a1.x += dot4(w0,x1[i]); a1.y += dot4(w1,x1[i]); a1.z += dot4(w2,x1[i]); a1.w += dot4(w3,x1[i]);
        }
        v4[(size_t)p0*16 + g] = a0;
        v4[(size_t)(p0+1)*16 + g] = a1;
    }

    // pe stage 1 per pixel
    const float4* sw14 = (const float4*)sw1;
    float4* t14 = (float4*)g_t1;
    #pragma unroll
    for (int px = 0; px < 2; px++) {
        int p = p0 + px;
        int b = p >> 16, s = p & 65535, y = s >> 8, xx = s & 255;
        float4 acc[16];
        #pragma unroll
        for (int g = 0; g < 16; g++) { acc[g].x=0; acc[g].y=0; acc[g].z=0; acc[g].w=0; }
        #pragma unroll
        for (int ky = 0; ky < 3; ky++) {
            int yy = y + ky - 1; if (yy < 0 || yy >= HH) continue;
            #pragma unroll
            for (int kx = 0; kx < 3; kx++) {
                int xc = xx + kx - 1; if (xc < 0 || xc >= WWD) continue;
                size_t np = (size_t)((b<<16) + (yy<<8) + xc);
                int tap = ky*3 + kx;
                #pragma unroll
                for (int g = 0; g < 16; g++) {
                    float4 v = x4[np*16+g], wv = sw14[tap*16+g];
                    acc[g].x += wv.x*v.x; acc[g].y += wv.y*v.y; acc[g].z += wv.z*v.z; acc[g].w += wv.w*v.w;
                }
            }
        }
        #pragma unroll
        for (int g = 0; g < 16; g++) {
            float4 r;
            r.x = geluf(acc[g].x); r.y = geluf(acc[g].y); r.z = geluf(acc[g].z); r.w = geluf(acc[g].w);
            t14[(size_t)p*16 + g] = r;
        }
    }
}

// -------- fused output: gate = m1*(1+sig(dw5(m2))); y = Wfold*(v*gate) + bp + dw3(t1) --------
__global__ __launch_bounds__(128) void k_outf(const float* __restrict__ bp,
                                              const float* __restrict__ pe_w2,
                                              const float* __restrict__ dw,
                                              const float* __restrict__ dwb,
                                              float* __restrict__ out)
{
    __shared__ float sdw[25*CC];
    __shared__ float sdb[CC];
    __shared__ float4 sW[CC*16];
    __shared__ float  sb[CC];
    __shared__ float  sw2[9*CC];
    int b = blockIdx.y;
    int row = blockIdx.x;
    for (int t = threadIdx.x; t < 25*CC; t += 128) { int c = t/25, k = t%25; sdw[k*CC+c] = dw[c*25+k]; }
    for (int t = threadIdx.x; t < CC; t += 128) { sdb[t] = dwb[t]; sb[t] = bp[t]; }
    for (int t = threadIdx.x; t < CC*16; t += 128) sW[t] = ((const float4*)(g_wfold + b*4096))[t];
    for (int t = threadIdx.x; t < 9*CC; t += 128) { int c = t/9, k = t%9; sw2[k*CC+c] = pe_w2[c*9+k]; }
    __syncthreads();

    int x0i = threadIdx.x*2;
    const float4* m24 = (const float4*)g_m2;
    const float4* m14 = (const float4*)g_m1;
    const float4* v4  = (const float4*)g_v;
    const float4* sdw4 = (const float4*)sdw;

    float4 gv[2][16];
    #pragma unroll
    for (int px = 0; px < 2; px++) {
        int xx = x0i + px;
        size_t p = (size_t)b*PIXB + row*256 + xx;
        float4 acc[16];
        #pragma unroll
        for (int g = 0; g < 16; g++) { acc[g].x=sdb[4*g]; acc[g].y=sdb[4*g+1]; acc[g].z=sdb[4*g+2]; acc[g].w=sdb[4*g+3]; }
        for (int ky = 0; ky < 5; ky++) {
            int yy = row + ky - 2; if (yy < 0 || yy >= HH) continue;
            for (int kx = 0; kx < 5; kx++) {
                int xc = xx + kx - 2; if (xc < 0 || xc >= WWD) continue;
                size_t np = (size_t)b*PIXB + (yy<<8) + xc;
                int tap = ky*5 + kx;
                #pragma unroll
                for (int g = 0; g < 16; g++) {
                    float4 mv = m24[np*16+g], wv = sdw4[tap*16+g];
                    acc[g].x += wv.x*mv.x; acc[g].y += wv.y*mv.y; acc[g].z += wv.z*mv.z; acc[g].w += wv.w*mv.w;
                }
            }
        }
        #pragma unroll
        for (int g = 0; g < 16; g++) {
            float4 m1v = m14[p*16+g], vv = v4[p*16+g];
            gv[px][g].x = vv.x * (m1v.x * (1.f + sigmf(acc[g].x)));
            gv[px][g].y = vv.y * (m1v.y * (1.f + sigmf(acc[g].y)));
            gv[px][g].z = vv.z * (m1v.z * (1.f + sigmf(acc[g].z)));
            gv[px][g].w = vv.w * (m1v.w * (1.f + sigmf(acc[g].w)));
        }
    }

    // precompute valid tap pixel offsets for the 3x3
    int nps0[9], nps1[9];
    #pragma unroll
    for (int t = 0; t < 9; t++) {
        int ky = t/3, kx = t%3;
        int yy = row + ky - 1;
        int xc0 = x0i + kx - 1;
        int xc1 = x0i + 1 + kx - 1;
        nps0[t] = (yy >= 0 && yy < HH && xc0 >= 0 && xc0 < WWD) ? (int)((yy<<8) + xc0) : -1;
        nps1[t] = (yy >= 0 && yy < HH && xc1 >= 0 && xc1 < WWD) ? (int)((yy<<8) + xc1) : -1;
    }

    const float4* t14 = (const float4*)g_t1;
    const float4* sw24 = (const float4*)sw2;
    float4* out4 = (float4*)out;
    size_t p0 = (size_t)b*PIXB + row*256 + x0i;
    size_t bbase = (size_t)b*PIXB;

    for (int g = 0; g < 16; g++) {
        float4 a0, a1;
        a0.x = sb[4*g]; a0.y = sb[4*g+1]; a0.z = sb[4*g+2]; a0.w = sb[4*g+3];
        a1 = a0;
        #pragma unroll
        for (int i = 0; i < 16; i++) {
            float4 w0 = sW[(g*4+0)*16+i];
            float4 w1 = sW[(g*4+1)*16+i];
            float4 w2 = sW[(g*4+2)*16+i];
            float4 w3 = sW[(g*4+3)*16+i];
            a0.x += dot4(w0,gv[0][i]); a0.y += dot4(w1,gv[0][i]); a0.z += dot4(w2,gv[0][i]); a0.w += dot4(w3,gv[0][i]);
            a1.x += dot4(w0,gv[1][i]); a1.y += dot4(w1,gv[1][i]); a1.z += dot4(w2,gv[1][i]); a1.w += dot4(w3,gv[1][i]);
        }
        #pragma unroll
        for (int t = 0; t < 9; t++) {
            float4 wv = sw24[t*16+g];
            if (nps0[t] >= 0) {
                float4 tv = t14[(bbase + nps0[t])*16+g];
                a0.x += wv.x*tv.x; a0.y += wv.y*tv.y; a0.z += wv.z*tv.z; a0.w += wv.w*tv.w;
            }
            if (nps1[t] >= 0) {
                float4 tv = t14[(bbase + nps1[t])*16+g];
                a1.x += wv.x*tv.x; a1.y += wv.y*tv.y; a1.z += wv.z*tv.z; a1.w += wv.w*tv.w;
            }
        }
        out4[p0*16 + g] = a0;
        out4[(p0+1)*16 + g] = a1;
    }
}

// ---------------- launcher ----------------
extern "C" void kernel_launch(void* const* d_in, const int* in_sizes, int n_in,
                              void* d_out, int out_size)
{
    const float* x_in   = (const float*)d_in[0];
    const float* mask   = (const float*)d_in[1];
    const float* Wq     = (const float*)d_in[2];
    const float* Wk     = (const float*)d_in[3];
    const float* Wv     = (const float*)d_in[4];
    const float* rescale= (const float*)d_in[5];
    const float* Wp     = (const float*)d_in[6];
    const float* bp     = (const float*)d_in[7];
    const float* mm_w1  = (const float*)d_in[8];
    const float* mm_b1  = (const float*)d_in[9];
    const float* mm_w2  = (const float*)d_in[10];
    const float* mm_b2  = (const float*)d_in[11];
    const float* mm_dw  = (const float*)d_in[12];
    const float* mm_dwb = (const float*)d_in[13];
    const float* pe_w1  = (const float*)d_in[14];
    const float* pe_w2  = (const float*)d_in[15];
    float* out = (float*)d_out;

    float *pm1, *pm2;
    cudaGetSymbolAddress((void**)&pm1, g_m1);
    cudaGetSymbolAddress((void**)&pm2, g_m2);

    // q/k path collapses to the Gram matrix of x
    k_gram_part<<<NCHUNK, 256>>>(x_in);
    k_gram_reduce<<<(BN*4096 + 255)/256, 256>>>();
    k_small2<<<BN, 256>>>(Wq, Wk, Wp, rescale);

    // mask path matvecs
    k_matvec<<<NPIX/(128*2), 128>>>(mask, mm_w1, mm_b1, pm1);
    k_matvec<<<NPIX/(128*2), 128>>>(pm1,  mm_w2, mm_b2, pm2);

    // fused x path: v + pe stage 1
    k_xv<<<NPIX/256, 128>>>(x_in, Wv, pe_w1);

    // fused gate + projection + pe stage 2
    k_outf<<<dim3(HH, BN), 128>>>(bp, pe_w2, mm_dw, mm_dwb, out);
}

// round 3
// speedup vs baseline: 1.3775x; 1.3775x over previous
#include <cuda_runtime.h>
#include <math.h>

#define BN 2
#define HH 256
#define WWD 256
#define CC 64
#define PIXB (HH*WWD)          // 65536 pixels per batch
#define NPIX (BN*PIXB)         // 131072
#define NCHUNK 512

// ---------------- device scratch ----------------
__device__ float g_v [NPIX*CC];
__device__ float g_m1[NPIX*CC];
__device__ float g_m2[NPIX*CC];
__device__ float g_t1[NPIX*CC];
__device__ float g_t2[NPIX*CC];
__device__ float g_vm[NPIX*CC];
__device__ float g_gpart[NCHUNK*4096];
__device__ float g_gram [BN*4096];
__device__ float g_wfold[BN*4096];

__device__ __forceinline__ float sigmf(float x) {
    return 1.0f / (1.0f + __expf(-x));
}
__device__ __forceinline__ float geluf(float v) {
    return 0.5f * v * (1.0f + erff(v * 0.70710678118654752f));
}

// ---------------- Gram partials: G_b = sum_n x x^T ----------------
__global__ __launch_bounds__(256) void k_gram_part(const float* __restrict__ x)
{
    __shared__ float sx[8][64];
    int chunk = blockIdx.x;
    int base  = chunk * 256;
    int tid = threadIdx.x;
    int ti = tid >> 4, tj = tid & 15;
    float a00=0,a01=0,a02=0,a03=0, a10=0,a11=0,a12=0,a13=0;
    float a20=0,a21=0,a22=0,a23=0, a30=0,a31=0,a32=0,a33=0;

    for (int pp = 0; pp < 256; pp += 8) {
        __syncthreads();
        int idx = tid * 2;
        int pr = idx >> 6, cc = idx & 63;
        float2 v2 = *(const float2*)&x[(size_t)(base + pp + pr)*CC + cc];
        sx[pr][cc] = v2.x; sx[pr][cc+1] = v2.y;
        __syncthreads();
        #pragma unroll
        for (int p = 0; p < 8; p++) {
            float4 xi = *(const float4*)&sx[p][4*ti];
            float4 xj = *(const float4*)&sx[p][4*tj];
            a00 += xi.x*xj.x; a01 += xi.x*xj.y; a02 += xi.x*xj.z; a03 += xi.x*xj.w;
            a10 += xi.y*xj.x; a11 += xi.y*xj.y; a12 += xi.y*xj.z; a13 += xi.y*xj.w;
            a20 += xi.z*xj.x; a21 += xi.z*xj.y; a22 += xi.z*xj.z; a23 += xi.z*xj.w;
            a30 += xi.w*xj.x; a31 += xi.w*xj.y; a32 += xi.w*xj.z; a33 += xi.w*xj.w;
        }
    }
    float* dst = &g_gpart[(size_t)chunk*4096];
    int r = 4*ti, c = 4*tj;
    dst[(r+0)*64+c+0]=a00; dst[(r+0)*64+c+1]=a01; dst[(r+0)*64+c+2]=a02; dst[(r+0)*64+c+3]=a03;
    dst[(r+1)*64+c+0]=a10; dst[(r+1)*64+c+1]=a11; dst[(r+1)*64+c+2]=a12; dst[(r+1)*64+c+3]=a13;
    dst[(r+2)*64+c+0]=a20; dst[(r+2)*64+c+1]=a21; dst[(r+2)*64+c+2]=a22; dst[(r+2)*64+c+3]=a23;
    dst[(r+3)*64+c+0]=a30; dst[(r+3)*64+c+1]=a31; dst[(r+3)*64+c+2]=a32; dst[(r+3)*64+c+3]=a33;
}

__global__ void k_gram_reduce()
{
    int e = blockIdx.x*blockDim.x + threadIdx.x;
    if (e >= BN*4096) return;
    int b = e >> 12, i = e & 4095;
    float s = 0.f;
    for (int c = 0; c < NCHUNK/BN; c++)
        s += g_gpart[(size_t)(b*(NCHUNK/BN)+c)*4096 + i];
    g_gram[e] = s;
}

// ---------------- tiny solve: attn from Gram, fold Wp*A -> g_wfold ----------------
__global__ __launch_bounds__(256) void k_small2(const float* __restrict__ Wq,
                                                const float* __restrict__ Wk,
                                                const float* __restrict__ Wp,
                                                const float* __restrict__ rs)
{
    __shared__ float sG[4096];
    __shared__ float sGq[4096];
    __shared__ float sLog[1024];
    __shared__ float sNq[64], sNk[64];
    __shared__ float sPart[256];
    int b = blockIdx.x;
    int tid = threadIdx.x;

    for (int t = tid; t < 4096; t += 256) sG[t] = g_gram[b*4096 + t];
    __syncthreads();
    for (int t = tid; t < 4096; t += 256) {
        int c = t >> 6, o = t & 63;
        float s = 0.f;
        #pragma unroll 8
        for (int i = 0; i < 64; i++) s += sG[c*64+i] * Wq[o*64+i];
        sGq[t] = s;
    }
    __syncthreads();
    {
        int o = tid >> 2, part = tid & 3;
        float kp = 0.f;
        for (int c = part*16; c < part*16 + 16; c++) {
            float gk = 0.f;
            #pragma unroll 8
            for (int i = 0; i < 64; i++) gk += sG[c*64+i] * Wk[o*64+i];
            kp += Wk[o*64+c] * gk;
        }
        sPart[tid] = kp;
    }
    __syncthreads();
    if (tid < 64) {
        int o = tid;
        float qq = 0.f;
        #pragma unroll 8
        for (int c = 0; c < 64; c++) qq += Wq[o*64+c] * sGq[c*64+o];
        sNq[o] = fmaxf(sqrtf(fmaxf(qq, 0.f)), 1e-12f);
        float kk = sPart[4*o] + sPart[4*o+1] + sPart[4*o+2] + sPart[4*o+3];
        sNk[o] = fmaxf(sqrtf(fmaxf(kk, 0.f)), 1e-12f);
    }
    __syncthreads();
    for (int t = tid; t < 1024; t += 256) {
        int h = t >> 8, d = (t >> 4) & 15, e = t & 15;
        int rk = h*16 + d, rq = h*16 + e;
        float s = 0.f;
        #pragma unroll 8
        for (int c = 0; c < 64; c++) s += Wk[rk*64+c] * sGq[c*64+rq];
        sLog[t] = s / (sNk[rk] * sNq[rq]) * rs[h];
    }
    __syncthreads();
    if (tid < 64) {
        float* row = &sLog[tid*16];
        float m = row[0];
        for (int e = 1; e < 16; e++) m = fmaxf(m, row[e]);
        float sum = 0.f;
        for (int e = 0; e < 16; e++) { float ev = expf(row[e]-m); row[e] = ev; sum += ev; }
        float inv = 1.f / sum;
        for (int e = 0; e < 16; e++) row[e] *= inv;
    }
    __syncthreads();
    for (int t = tid; t < 4096; t += 256) {
        int o = t >> 6, j = t & 63, hj = j >> 4, ej = j & 15;
        float s = 0.f;
        #pragma unroll
        for (int d = 0; d < 16; d++)
            s += Wp[o*64 + hj*16 + d] * sLog[(hj*16 + d)*16 + ej];
        g_wfold[b*4096 + t] = s;
    }
}

// ---------------- output-stationary matvec: y = W x (+bias) (+add) ----------------
// block = 256 thr (8 warps), tile = 128 pixels. Lane l owns output rows l and l+32.
// W in registers; pixels staged through smem, read via broadcast LDS.
// wsel: 0 -> single W for all blocks; 1 -> W + (block>=gridDim/2)*4096 (per-batch fold)
__global__ __launch_bounds__(256) void k_mv_os(const float* __restrict__ in,
                                               const float* __restrict__ Wg,
                                               const float* __restrict__ bias,
                                               const float* __restrict__ add,
                                               float* __restrict__ out,
                                               int wsel)
{
    __shared__ float sx[128*64];   // 32 KB (also reused to stage W at start)
    int tid = threadIdx.x, lane = tid & 31, wid = tid >> 5;
    const float* W = Wg + (wsel ? (int)(blockIdx.x >> 9) * 4096 : 0);

    // stage W (64x64) into smem with pad-68 rows, coalesced
    for (int t = tid; t < 4096; t += 256) sx[(t >> 6)*68 + (t & 63)] = W[t];
    __syncthreads();
    float w0[64], w1[64];
    #pragma unroll
    for (int k = 0; k < 16; k++) {
        float4 a = *(const float4*)&sx[lane*68 + 4*k];
        w0[4*k+0]=a.x; w0[4*k+1]=a.y; w0[4*k+2]=a.z; w0[4*k+3]=a.w;
        float4 b2 = *(const float4*)&sx[(lane+32)*68 + 4*k];
        w1[4*k+0]=b2.x; w1[4*k+1]=b2.y; w1[4*k+2]=b2.z; w1[4*k+3]=b2.w;
    }
    float bb0 = bias ? bias[lane]      : 0.f;
    float bb1 = bias ? bias[lane + 32] : 0.f;
    __syncthreads();

    // load 128-pixel tile, coalesced
    size_t pbase = (size_t)blockIdx.x * 128;
    const float4* in4 = (const float4*)in + pbase*16;
    float4* sx4 = (float4*)sx;
    #pragma unroll
    for (int j = 0; j < 8; j++) sx4[tid + 256*j] = in4[tid + 256*j];
    __syncthreads();

    // compute: warp wid owns pixels wid*16 .. wid*16+15, two at a time
    for (int i = 0; i < 16; i += 2) {
        int p0 = wid*16 + i, p1 = p0 + 1;
        float a00 = bb0, a01 = bb1, a10 = bb0, a11 = bb1;
        #pragma unroll
        for (int k4 = 0; k4 < 16; k4++) {
            float4 xa = *(const float4*)&sx[p0*64 + 4*k4];   // broadcast
            float4 xb = *(const float4*)&sx[p1*64 + 4*k4];   // broadcast
            a00 = fmaf(w0[4*k4+0], xa.x, a00); a00 = fmaf(w0[4*k4+1], xa.y, a00);
            a00 = fmaf(w0[4*k4+2], xa.z, a00); a00 = fmaf(w0[4*k4+3], xa.w, a00);
            a01 = fmaf(w1[4*k4+0], xa.x, a01); a01 = fmaf(w1[4*k4+1], xa.y, a01);
            a01 = fmaf(w1[4*k4+2], xa.z, a01); a01 = fmaf(w1[4*k4+3], xa.w, a01);
            a10 = fmaf(w0[4*k4+0], xb.x, a10); a10 = fmaf(w0[4*k4+1], xb.y, a10);
            a10 = fmaf(w0[4*k4+2], xb.z, a10); a10 = fmaf(w0[4*k4+3], xb.w, a10);
            a11 = fmaf(w1[4*k4+0], xb.x, a11); a11 = fmaf(w1[4*k4+1], xb.y, a11);
            a11 = fmaf(w1[4*k4+2], xb.z, a11); a11 = fmaf(w1[4*k4+3], xb.w, a11);
        }
        size_t o0 = (pbase + p0)*64, o1 = (pbase + p1)*64;
        if (add) {
            a00 += add[o0 + lane]; a01 += add[o0 + 32 + lane];
            a10 += add[o1 + lane]; a11 += add[o1 + 32 + lane];
        }
        out[o0 + lane]      = a00;
        out[o0 + 32 + lane] = a01;
        out[o1 + lane]      = a10;
        out[o1 + 32 + lane] = a11;
    }
}

// ---------------- g-fast dwconv kernels: tid&15 = float4 channel group ----------------
// pe stage 1: t1 = gelu(dw3x3(x, pe_w1))
__global__ __launch_bounds__(256) void k_pe1_g(const float* __restrict__ x,
                                               const float* __restrict__ w)
{
    __shared__ float sw[9*CC];
    for (int t = threadIdx.x; t < 9*CC; t += 256) { int c = t/9, k = t%9; sw[k*CC+c] = w[t]; }
    __syncthreads();
    int g  = threadIdx.x & 15;
    int pl = threadIdx.x >> 4;
    int p = blockIdx.x*16 + pl;
    int b = p >> 16, s = p & 65535, y = s >> 8, xx = s & 255;
    const float4* x4 = (const float4*)x;
    const float4* sw4 = (const float4*)sw;
    float4 acc = make_float4(0.f, 0.f, 0.f, 0.f);
    #pragma unroll
    for (int ky = 0; ky < 3; ky++) {
        int yy = y + ky - 1; if (yy < 0 || yy >= HH) continue;
        #pragma unroll
        for (int kx = 0; kx < 3; kx++) {
            int xc = xx + kx - 1; if (xc < 0 || xc >= WWD) continue;
            size_t np = (size_t)((b<<16) + (yy<<8) + xc);
            float4 v = x4[np*16 + g], wv = sw4[(ky*3+kx)*16 + g];
            acc.x = fmaf(wv.x, v.x, acc.x); acc.y = fmaf(wv.y, v.y, acc.y);
            acc.z = fmaf(wv.z, v.z, acc.z); acc.w = fmaf(wv.w, v.w, acc.w);
        }
    }
    float4 r;
    r.x = geluf(acc.x); r.y = geluf(acc.y); r.z = geluf(acc.z); r.w = geluf(acc.w);
    ((float4*)g_t1)[(size_t)p*16 + g] = r;
}

// pe stage 2: t2 = dw3x3(t1, pe_w2)
__global__ __launch_bounds__(256) void k_pe2_g(const float* __restrict__ w)
{
    __shared__ float sw[9*CC];
    for (int t = threadIdx.x; t < 9*CC; t += 256) { int c = t/9, k = t%9; sw[k*CC+c] = w[t]; }
    __syncthreads();
    int g  = threadIdx.x & 15;
    int pl = threadIdx.x >> 4;
    int p = blockIdx.x*16 + pl;
    int b = p >> 16, s = p & 65535, y = s >> 8, xx = s & 255;
    const float4* t14 = (const float4*)g_t1;
    const float4* sw4 = (const float4*)sw;
    float4 acc = make_float4(0.f, 0.f, 0.f, 0.f);
    #pragma unroll
    for (int ky = 0; ky < 3; ky++) {
        int yy = y + ky - 1; if (yy < 0 || yy >= HH) continue;
        #pragma unroll
        for (int kx = 0; kx < 3; kx++) {
            int xc = xx + kx - 1; if (xc < 0 || xc >= WWD) continue;
            size_t np = (size_t)((b<<16) + (yy<<8) + xc);
            float4 v = t14[np*16 + g], wv = sw4[(ky*3+kx)*16 + g];
            acc.x = fmaf(wv.x, v.x, acc.x); acc.y = fmaf(wv.y, v.y, acc.y);
            acc.z = fmaf(wv.z, v.z, acc.z); acc.w = fmaf(wv.w, v.w, acc.w);
        }
    }
    ((float4*)g_t2)[(size_t)p*16 + g] = acc;
}

// mask gate: vm = v * m1 * (1 + sigmoid(dw5x5(m2) + b))
__global__ __launch_bounds__(256) void k_ma_g(const float* __restrict__ dw,
                                              const float* __restrict__ dwb)
{
    __shared__ float sdw[25*CC];
    __shared__ float sdb[CC];
    for (int t = threadIdx.x; t < 25*CC; t += 256) { int c = t/25, k = t%25; sdw[k*CC+c] = dw[t]; }
    for (int t = threadIdx.x; t < CC; t += 256) sdb[t] = dwb[t];
    __syncthreads();
    int g  = threadIdx.x & 15;
    int pl = threadIdx.x >> 4;
    int p = blockIdx.x*16 + pl;
    int b = p >> 16, s = p & 65535, y = s >> 8, xx = s & 255;
    const float4* m24 = (const float4*)g_m2;
    const float4* sdw4 = (const float4*)sdw;
    float4 acc = ((const float4*)sdb)[g];
    for (int ky = 0; ky < 5; ky++) {
        int yy = y + ky - 2; if (yy < 0 || yy >= HH) continue;
        #pragma unroll
        for (int kx = 0; kx < 5; kx++) {
            int xc = xx + kx - 2; if (xc < 0 || xc >= WWD) continue;
            size_t np = (size_t)((b<<16) + (yy<<8) + xc);
            float4 mv = m24[np*16 + g], wv = sdw4[(ky*5+kx)*16 + g];
            acc.x = fmaf(wv.x, mv.x, acc.x); acc.y = fmaf(wv.y, mv.y, acc.y);
            acc.z = fmaf(wv.z, mv.z, acc.z); acc.w = fmaf(wv.w, mv.w, acc.w);
        }
    }
    float4 m1v = ((const float4*)g_m1)[(size_t)p*16 + g];
    float4 vv  = ((const float4*)g_v) [(size_t)p*16 + g];
    float4 r;
    r.x = vv.x * (m1v.x * (1.f + sigmf(acc.x)));
    r.y = vv.y * (m1v.y * (1.f + sigmf(acc.y)));
    r.z = vv.z * (m1v.z * (1.f + sigmf(acc.z)));
    r.w = vv.w * (m1v.w * (1.f + sigmf(acc.w)));
    ((float4*)g_vm)[(size_t)p*16 + g] = r;
}

// ---------------- launcher ----------------
extern "C" void kernel_launch(void* const* d_in, const int* in_sizes, int n_in,
                              void* d_out, int out_size)
{
    const float* x_in   = (const float*)d_in[0];
    const float* mask   = (const float*)d_in[1];
    const float* Wq     = (const float*)d_in[2];
    const float* Wk     = (const float*)d_in[3];
    const float* Wv     = (const float*)d_in[4];
    const float* rescale= (const float*)d_in[5];
    const float* Wp     = (const float*)d_in[6];
    const float* bp     = (const float*)d_in[7];
    const float* mm_w1  = (const float*)d_in[8];
    const float* mm_b1  = (const float*)d_in[9];
    const float* mm_w2  = (const float*)d_in[10];
    const float* mm_b2  = (const float*)d_in[11];
    const float* mm_dw  = (const float*)d_in[12];
    const float* mm_dwb = (const float*)d_in[13];
    const float* pe_w1  = (const float*)d_in[14];
    const float* pe_w2  = (const float*)d_in[15];
    float* out = (float*)d_out;

    float *pm1, *pm2, *pv, *pvm, *pt2, *pwf;
    cudaGetSymbolAddress((void**)&pm1, g_m1);
    cudaGetSymbolAddress((void**)&pm2, g_m2);
    cudaGetSymbolAddress((void**)&pv,  g_v);
    cudaGetSymbolAddress((void**)&pvm, g_vm);
    cudaGetSymbolAddress((void**)&pt2, g_t2);
    cudaGetSymbolAddress((void**)&pwf, g_wfold);

    // q/k path collapses to the Gram matrix of x
    k_gram_part<<<NCHUNK, 256>>>(x_in);
    k_gram_reduce<<<(BN*4096 + 255)/256, 256>>>();
    k_small2<<<BN, 256>>>(Wq, Wk, Wp, rescale);

    // per-pixel 64x64 matvecs (output-stationary)
    k_mv_os<<<NPIX/128, 256>>>(mask, mm_w1, mm_b1, nullptr, pm1, 0);
    k_mv_os<<<NPIX/128, 256>>>(pm1,  mm_w2, mm_b2, nullptr, pm2, 0);
    k_mv_os<<<NPIX/128, 256>>>(x_in, Wv, nullptr, nullptr, pv, 0);

    // spatial kernels (g-fast, coalesced)
    k_pe1_g<<<NPIX/16, 256>>>(x_in, pe_w1);
    k_pe2_g<<<NPIX/16, 256>>>(pe_w2);
    k_ma_g <<<NPIX/16, 256>>>(mm_dw, mm_dwb);

    // final: out = Wfold_b * vm + bp + t2
    k_mv_os<<<NPIX/128, 256>>>(pvm, pwf, bp, pt2, out, 1);
}

// round 4
// speedup vs baseline: 1.4319x; 1.0395x over previous
#include <cuda_runtime.h>
#include <math.h>

#define BN 2
#define HH 256
#define WWD 256
#define CC 64
#define PIXB (HH*WWD)
#define NPIX (BN*PIXB)
#define NCHUNK 512

// ---------------- device scratch ----------------
__device__ float g_v [NPIX*CC];
__device__ float g_m1[NPIX*CC];
__device__ float g_m2[NPIX*CC];
__device__ float g_t1[NPIX*CC];
__device__ float g_t2[NPIX*CC];
__device__ float g_vm[NPIX*CC];
__device__ float g_gpart[NCHUNK*4096];
__device__ float g_gram [BN*4096];
__device__ float g_wfold[BN*4096];
__device__ float g_w2f[4096];
__device__ float g_b2f[64];

__device__ __forceinline__ float sigmf(float x) {
    return 1.0f / (1.0f + __expf(-x));
}
__device__ __forceinline__ float geluf(float v) {
    return 0.5f * v * (1.0f + erff(v * 0.70710678118654752f));
}

// ---------------- Gram partials ----------------
__global__ __launch_bounds__(256) void k_gram_part(const float* __restrict__ x)
{
    __shared__ float sx[8][64];
    int chunk = blockIdx.x;
    int base  = chunk * 256;
    int tid = threadIdx.x;
    int ti = tid >> 4, tj = tid & 15;
    float a00=0,a01=0,a02=0,a03=0, a10=0,a11=0,a12=0,a13=0;
    float a20=0,a21=0,a22=0,a23=0, a30=0,a31=0,a32=0,a33=0;

    for (int pp = 0; pp < 256; pp += 8) {
        __syncthreads();
        int idx = tid * 2;
        int pr = idx >> 6, cc = idx & 63;
        float2 v2 = *(const float2*)&x[(size_t)(base + pp + pr)*CC + cc];
        sx[pr][cc] = v2.x; sx[pr][cc+1] = v2.y;
        __syncthreads();
        #pragma unroll
        for (int p = 0; p < 8; p++) {
            float4 xi = *(const float4*)&sx[p][4*ti];
            float4 xj = *(const float4*)&sx[p][4*tj];
            a00 += xi.x*xj.x; a01 += xi.x*xj.y; a02 += xi.x*xj.z; a03 += xi.x*xj.w;
            a10 += xi.y*xj.x; a11 += xi.y*xj.y; a12 += xi.y*xj.z; a13 += xi.y*xj.w;
            a20 += xi.z*xj.x; a21 += xi.z*xj.y; a22 += xi.z*xj.z; a23 += xi.z*xj.w;
            a30 += xi.w*xj.x; a31 += xi.w*xj.y; a32 += xi.w*xj.z; a33 += xi.w*xj.w;
        }
    }
    float* dst = &g_gpart[(size_t)chunk*4096];
    int r = 4*ti, c = 4*tj;
    dst[(r+0)*64+c+0]=a00; dst[(r+0)*64+c+1]=a01; dst[(r+0)*64+c+2]=a02; dst[(r+0)*64+c+3]=a03;
    dst[(r+1)*64+c+0]=a10; dst[(r+1)*64+c+1]=a11; dst[(r+1)*64+c+2]=a12; dst[(r+1)*64+c+3]=a13;
    dst[(r+2)*64+c+0]=a20; dst[(r+2)*64+c+1]=a21; dst[(r+2)*64+c+2]=a22; dst[(r+2)*64+c+3]=a23;
    dst[(r+3)*64+c+0]=a30; dst[(r+3)*64+c+1]=a31; dst[(r+3)*64+c+2]=a32; dst[(r+3)*64+c+3]=a33;
}

__global__ void k_gram_reduce()
{
    int e = blockIdx.x*blockDim.x + threadIdx.x;
    if (e >= BN*4096) return;
    int b = e >> 12, i = e & 4095;
    float s = 0.f;
    for (int c = 0; c < NCHUNK/BN; c++)
        s += g_gpart[(size_t)(b*(NCHUNK/BN)+c)*4096 + i];
    g_gram[e] = s;
}

// ---------------- fold W2*W1 and b2f = W2 b1 + b2 ----------------
__global__ __launch_bounds__(256) void k_fold(const float* __restrict__ W1,
                                              const float* __restrict__ b1,
                                              const float* __restrict__ W2,
                                              const float* __restrict__ b2)
{
    __shared__ float sW1[4096];
    int tid = threadIdx.x;
    for (int t = tid; t < 4096; t += 256) sW1[t] = W1[t];
    __syncthreads();
    for (int t = tid; t < 4096; t += 256) {
        int o = t >> 6, c = t & 63;
        float s = 0.f;
        #pragma unroll 8
        for (int i = 0; i < 64; i++) s += W2[o*64+i] * sW1[i*64+c];
        g_w2f[t] = s;
    }
    if (tid < 64) {
        float s = b2[tid];
        for (int i = 0; i < 64; i++) s += W2[tid*64+i] * b1[i];
        g_b2f[tid] = s;
    }
}

// ---------------- tiny solve: attn from Gram, fold Wp*A -> g_wfold ----------------
__global__ __launch_bounds__(256) void k_small2(const float* __restrict__ Wq,
                                                const float* __restrict__ Wk,
                                                const float* __restrict__ Wp,
                                                const float* __restrict__ rs)
{
    __shared__ float sG[4096];
    __shared__ float sGq[4096];
    __shared__ float sLog[1024];
    __shared__ float sNq[64], sNk[64];
    __shared__ float sPart[256];
    int b = blockIdx.x;
    int tid = threadIdx.x;

    for (int t = tid; t < 4096; t += 256) sG[t] = g_gram[b*4096 + t];
    __syncthreads();
    for (int t = tid; t < 4096; t += 256) {
        int c = t >> 6, o = t & 63;
        float s = 0.f;
        #pragma unroll 8
        for (int i = 0; i < 64; i++) s += sG[c*64+i] * Wq[o*64+i];
        sGq[t] = s;
    }
    __syncthreads();
    {
        int o = tid >> 2, part = tid & 3;
        float kp = 0.f;
        for (int c = part*16; c < part*16 + 16; c++) {
            float gk = 0.f;
            #pragma unroll 8
            for (int i = 0; i < 64; i++) gk += sG[c*64+i] * Wk[o*64+i];
            kp += Wk[o*64+c] * gk;
        }
        sPart[tid] = kp;
    }
    __syncthreads();
    if (tid < 64) {
        int o = tid;
        float qq = 0.f;
        #pragma unroll 8
        for (int c = 0; c < 64; c++) qq += Wq[o*64+c] * sGq[c*64+o];
        sNq[o] = fmaxf(sqrtf(fmaxf(qq, 0.f)), 1e-12f);
        float kk = sPart[4*o] + sPart[4*o+1] + sPart[4*o+2] + sPart[4*o+3];
        sNk[o] = fmaxf(sqrtf(fmaxf(kk, 0.f)), 1e-12f);
    }
    __syncthreads();
    for (int t = tid; t < 1024; t += 256) {
        int h = t >> 8, d = (t >> 4) & 15, e = t & 15;
        int rk = h*16 + d, rq = h*16 + e;
        float s = 0.f;
        #pragma unroll 8
        for (int c = 0; c < 64; c++) s += Wk[rk*64+c] * sGq[c*64+rq];
        sLog[t] = s / (sNk[rk] * sNq[rq]) * rs[h];
    }
    __syncthreads();
    if (tid < 64) {
        float* row = &sLog[tid*16];
        float m = row[0];
        for (int e = 1; e < 16; e++) m = fmaxf(m, row[e]);
        float sum = 0.f;
        for (int e = 0; e < 16; e++) { float ev = expf(row[e]-m); row[e] = ev; sum += ev; }
        float inv = 1.f / sum;
        for (int e = 0; e < 16; e++) row[e] *= inv;
    }
    __syncthreads();
    for (int t = tid; t < 4096; t += 256) {
        int o = t >> 6, j = t & 63, hj = j >> 4, ej = j & 15;
        float s = 0.f;
        #pragma unroll
        for (int d = 0; d < 16; d++)
            s += Wp[o*64 + hj*16 + d] * sLog[(hj*16 + d)*16 + ej];
        g_wfold[b*4096 + t] = s;
    }
}

// ---------------- matvec, one W-row per lane ----------------
// 256 thr = 8 warps: group = wid>>2 (rows grp*32+lane), warp wid&3 owns 32 of the
// 128-pixel tile, processed in quads of 4 (independent acc chains).
__global__ __launch_bounds__(256) void k_mv_b(const float* __restrict__ in,
                                              const float* __restrict__ Wg,
                                              const float* __restrict__ bias,
                                              const float* __restrict__ add,
                                              float* __restrict__ out,
                                              int wsel)
{
    __shared__ float4 sx4[2048];              // 32 KB
    float* sx = (float*)sx4;
    int tid = threadIdx.x, lane = tid & 31, wid = tid >> 5;
    int grp = wid >> 2;
    int row = grp*32 + lane;
    const float* W = Wg + (wsel ? (int)(blockIdx.x >> 9) * 4096 : 0);

    // stage W (pad-68 rows) and read own row into regs
    for (int t = tid; t < 4096; t += 256) sx[(t >> 6)*68 + (t & 63)] = W[t];
    __syncthreads();
    float w[64];
    #pragma unroll
    for (int k = 0; k < 16; k++) {
        float4 a = *(const float4*)&sx[row*68 + 4*k];
        w[4*k+0]=a.x; w[4*k+1]=a.y; w[4*k+2]=a.z; w[4*k+3]=a.w;
    }
    float bb = bias ? bias[row] : 0.f;
    __syncthreads();

    // load 128-pixel tile, coalesced
    size_t pbase = (size_t)blockIdx.x * 128;
    const float4* in4 = (const float4*)in + pbase*16;
    #pragma unroll
    for (int j = 0; j < 8; j++) sx4[tid + 256*j] = in4[tid + 256*j];
    __syncthreads();

    int pw = (wid & 3) * 32;
    #pragma unroll 2
    for (int q = 0; q < 8; q++) {
        int p0 = pw + q*4;
        float a0 = bb, a1 = bb, a2 = bb, a3 = bb;
        #pragma unroll
        for (int k4 = 0; k4 < 16; k4++) {
            float4 x0 = *(const float4*)&sx[(p0+0)*64 + 4*k4];
            float4 x1 = *(const float4*)&sx[(p0+1)*64 + 4*k4];
            float4 x2 = *(const float4*)&sx[(p0+2)*64 + 4*k4];
            float4 x3 = *(const float4*)&sx[(p0+3)*64 + 4*k4];
            a0 = fmaf(w[4*k4+0], x0.x, a0); a0 = fmaf(w[4*k4+1], x0.y, a0);
            a0 = fmaf(w[4*k4+2], x0.z, a0); a0 = fmaf(w[4*k4+3], x0.w, a0);
            a1 = fmaf(w[4*k4+0], x1.x, a1); a1 = fmaf(w[4*k4+1], x1.y, a1);
            a1 = fmaf(w[4*k4+2], x1.z, a1); a1 = fmaf(w[4*k4+3], x1.w, a1);
            a2 = fmaf(w[4*k4+0], x2.x, a2); a2 = fmaf(w[4*k4+1], x2.y, a2);
            a2 = fmaf(w[4*k4+2], x2.z, a2); a2 = fmaf(w[4*k4+3], x2.w, a2);
            a3 = fmaf(w[4*k4+0], x3.x, a3); a3 = fmaf(w[4*k4+1], x3.y, a3);
            a3 = fmaf(w[4*k4+2], x3.z, a3); a3 = fmaf(w[4*k4+3], x3.w, a3);
        }
        size_t o0 = (pbase + p0)*64 + row;
        if (add) {
            a0 += add[o0]; a1 += add[o0+64]; a2 += add[o0+128]; a3 += add[o0+192];
        }
        out[o0]     = a0;
        out[o0+64]  = a1;
        out[o0+128] = a2;
        out[o0+192] = a3;
    }
}

// ---------------- dwconv, 4-pixel strips, channel-group fast ----------------
// pe stage 1: t1 = gelu(dw3x3(x, pe_w1))
__global__ __launch_bounds__(256) void k_pe1_s(const float* __restrict__ x,
                                               const float* __restrict__ w)
{
    __shared__ float sw[9*CC];
    for (int t = threadIdx.x; t < 9*CC; t += 256) { int c = t/9, k = t%9; sw[k*CC+c] = w[t]; }
    __syncthreads();
    int g = threadIdx.x & 15, strip = threadIdx.x >> 4;
    int pbase = blockIdx.x*64 + strip*4;
    int b = pbase >> 16, s = pbase & 65535, y = s >> 8, x0 = s & 255;
    const float4* x4 = (const float4*)x;
    const float4* sw4 = (const float4*)sw;
    float4 acc[4];
    #pragma unroll
    for (int p = 0; p < 4; p++) acc[p] = make_float4(0.f,0.f,0.f,0.f);
    size_t bb = (size_t)(b << 16);
    #pragma unroll
    for (int ky = 0; ky < 3; ky++) {
        int yy = y + ky - 1; if (yy < 0 || yy >= HH) continue;
        #pragma unroll
        for (int c = -1; c <= 4; c++) {
            int xc = x0 + c; if (xc < 0 || xc >= WWD) continue;
            float4 v = x4[(bb + (yy<<8) + xc)*16 + g];
            #pragma unroll
            for (int p = 0; p < 4; p++) {
                int kx = c - p + 1; if (kx < 0 || kx > 2) continue;
                float4 wv = sw4[(ky*3+kx)*16 + g];
                acc[p].x = fmaf(wv.x, v.x, acc[p].x); acc[p].y = fmaf(wv.y, v.y, acc[p].y);
                acc[p].z = fmaf(wv.z, v.z, acc[p].z); acc[p].w = fmaf(wv.w, v.w, acc[p].w);
            }
        }
    }
    float4* t14 = (float4*)g_t1;
    #pragma unroll
    for (int p = 0; p < 4; p++) {
        float4 r;
        r.x = geluf(acc[p].x); r.y = geluf(acc[p].y);
        r.z = geluf(acc[p].z); r.w = geluf(acc[p].w);
        t14[(size_t)(pbase+p)*16 + g] = r;
    }
}

// pe stage 2: t2 = dw3x3(t1, pe_w2)
__global__ __launch_bounds__(256) void k_pe2_s(const float* __restrict__ w)
{
    __shared__ float sw[9*CC];
    for (int t = threadIdx.x; t < 9*CC; t += 256) { int c = t/9, k = t%9; sw[k*CC+c] = w[t]; }
    __syncthreads();
    int g = threadIdx.x & 15, strip = threadIdx.x >> 4;
    int pbase = blockIdx.x*64 + strip*4;
    int b = pbase >> 16, s = pbase & 65535, y = s >> 8, x0 = s & 255;
    const float4* t14 = (const float4*)g_t1;
    const float4* sw4 = (const float4*)sw;
    float4 acc[4];
    #pragma unroll
    for (int p = 0; p < 4; p++) acc[p] = make_float4(0.f,0.f,0.f,0.f);
    size_t bb = (size_t)(b << 16);
    #pragma unroll
    for (int ky = 0; ky < 3; ky++) {
        int yy = y + ky - 1; if (yy < 0 || yy >= HH) continue;
        #pragma unroll
        for (int c = -1; c <= 4; c++) {
            int xc = x0 + c; if (xc < 0 || xc >= WWD) continue;
            float4 v = t14[(bb + (yy<<8) + xc)*16 + g];
            #pragma unroll
            for (int p = 0; p < 4; p++) {
                int kx = c - p + 1; if (kx < 0 || kx > 2) continue;
                float4 wv = sw4[(ky*3+kx)*16 + g];
                acc[p].x = fmaf(wv.x, v.x, acc[p].x); acc[p].y = fmaf(wv.y, v.y, acc[p].y);
                acc[p].z = fmaf(wv.z, v.z, acc[p].z); acc[p].w = fmaf(wv.w, v.w, acc[p].w);
            }
        }
    }
    float4* t24 = (float4*)g_t2;
    #pragma unroll
    for (int p = 0; p < 4; p++) t24[(size_t)(pbase+p)*16 + g] = acc[p];
}

// mask gate: vm = v * m1 * (1 + sigmoid(dw5x5(m2) + b))
__global__ __launch_bounds__(256) void k_ma_s(const float* __restrict__ dw,
                                              const float* __restrict__ dwb)
{
    __shared__ float sdw[25*CC];
    __shared__ float sdb[CC];
    for (int t = threadIdx.x; t < 25*CC; t += 256) { int c = t/25, k = t%25; sdw[k*CC+c] = dw[t]; }
    for (int t = threadIdx.x; t < CC; t += 256) sdb[t] = dwb[t];
    __syncthreads();
    int g = threadIdx.x & 15, strip = threadIdx.x >> 4;
    int pbase = blockIdx.x*64 + strip*4;
    int b = pbase >> 16, s = pbase & 65535, y = s >> 8, x0 = s & 255;
    const float4* m24 = (const float4*)g_m2;
    const float4* sdw4 = (const float4*)sdw;
    float4 bias4 = ((const float4*)sdb)[g];
    float4 acc[4];
    #pragma unroll
    for (int p = 0; p < 4; p++) acc[p] = bias4;
    size_t bb = (size_t)(b << 16);
    #pragma unroll
    for (int ky = 0; ky < 5; ky++) {
        int yy = y + ky - 2; if (yy < 0 || yy >= HH) continue;
        #pragma unroll
        for (int c = -2; c <= 5; c++) {
            int xc = x0 + c; if (xc < 0 || xc >= WWD) continue;
            float4 v = m24[(bb + (yy<<8) + xc)*16 + g];
            #pragma unroll
            for (int p = 0; p < 4; p++) {
                int kx = c - p + 2; if (kx < 0 || kx > 4) continue;
                float4 wv = sdw4[(ky*5+kx)*16 + g];
                acc[p].x = fmaf(wv.x, v.x, acc[p].x); acc[p].y = fmaf(wv.y, v.y, acc[p].y);
                acc[p].z = fmaf(wv.z, v.z, acc[p].z); acc[p].w = fmaf(wv.w, v.w, acc[p].w);
            }
        }
    }
    const float4* m14 = (const float4*)g_m1;
    const float4* v4  = (const float4*)g_v;
    float4* vm4 = (float4*)g_vm;
    #pragma unroll
    for (int p = 0; p < 4; p++) {
        size_t idx = (size_t)(pbase+p)*16 + g;
        float4 m1v = m14[idx], vv = v4[idx];
        float4 r;
        r.x = vv.x * (m1v.x * (1.f + sigmf(acc[p].x)));
        r.y = vv.y * (m1v.y * (1.f + sigmf(acc[p].y)));
        r.z = vv.z * (m1v.z * (1.f + sigmf(acc[p].z)));
        r.w = vv.w * (m1v.w * (1.f + sigmf(acc[p].w)));
        vm4[idx] = r;
    }
}

// ---------------- launcher ----------------
extern "C" void kernel_launch(void* const* d_in, const int* in_sizes, int n_in,
                              void* d_out, int out_size)
{
    const float* x_in   = (const float*)d_in[0];
    const float* mask   = (const float*)d_in[1];
    const float* Wq     = (const float*)d_in[2];
    const float* Wk     = (const float*)d_in[3];
    const float* Wv     = (const float*)d_in[4];
    const float* rescale= (const float*)d_in[5];
    const float* Wp     = (const float*)d_in[6];
    const float* bp     = (const float*)d_in[7];
    const float* mm_w1  = (const float*)d_in[8];
    const float* mm_b1  = (const float*)d_in[9];
    const float* mm_w2  = (const float*)d_in[10];
    const float* mm_b2  = (const float*)d_in[11];
    const float* mm_dw  = (const float*)d_in[12];
    const float* mm_dwb = (const float*)d_in[13];
    const float* pe_w1  = (const float*)d_in[14];
    const float* pe_w2  = (const float*)d_in[15];
    float* out = (float*)d_out;

    float *pm1, *pm2, *pv, *pvm, *pt2, *pwf, *pw2f, *pb2f;
    cudaGetSymbolAddress((void**)&pm1,  g_m1);
    cudaGetSymbolAddress((void**)&pm2,  g_m2);
    cudaGetSymbolAddress((void**)&pv,   g_v);
    cudaGetSymbolAddress((void**)&pvm,  g_vm);
    cudaGetSymbolAddress((void**)&pt2,  g_t2);
    cudaGetSymbolAddress((void**)&pwf,  g_wfold);
    cudaGetSymbolAddress((void**)&pw2f, g_w2f);
    cudaGetSymbolAddress((void**)&pb2f, g_b2f);

    // tiny folds + Gram chain
    k_fold<<<1, 256>>>(mm_w1, mm_b1, mm_w2, mm_b2);
    k_gram_part<<<NCHUNK, 256>>>(x_in);
    k_gram_reduce<<<(BN*4096 + 255)/256, 256>>>();
    k_small2<<<BN, 256>>>(Wq, Wk, Wp, rescale);

    // per-pixel 64x64 matvecs
    k_mv_b<<<NPIX/128, 256>>>(mask, mm_w1, mm_b1, nullptr, pm1, 0);
    k_mv_b<<<NPIX/128, 256>>>(mask, pw2f, pb2f, nullptr, pm2, 0);
    k_mv_b<<<NPIX/128, 256>>>(x_in, Wv, nullptr, nullptr, pv, 0);

    // spatial kernels (4-pixel strips)
    k_pe1_s<<<NPIX/64, 256>>>(x_in, pe_w1);
    k_pe2_s<<<NPIX/64, 256>>>(pe_w2);
    k_ma_s <<<NPIX/64, 256>>>(mm_dw, mm_dwb);

    // final: out = Wfold_b * vm + bp + t2
    k_mv_b<<<NPIX/128, 256>>>(pvm, pwf, bp, pt2, out, 1);
}

// round 5
// speedup vs baseline: 1.8678x; 1.3044x over previous
#include <cuda_runtime.h>
#include <math.h>

#define BN 2
#define HH 256
#define WWD 256
#define CC 64
#define PIXB (HH*WWD)
#define NPIX (BN*PIXB)
#define NCHUNK 512

// ---------------- device scratch ----------------
__device__ float g_v [NPIX*CC];
__device__ float g_m1[NPIX*CC];
__device__ float g_m2[NPIX*CC];
__device__ float g_t1[NPIX*CC];
__device__ float g_t2[NPIX*CC];
__device__ float g_vm[NPIX*CC];
__device__ float g_gpart[NCHUNK*4096];
__device__ float g_gpart2[32*4096];
__device__ float g_gram [BN*4096];
__device__ float g_wfold[BN*4096];
__device__ float g_w2f[4096];
__device__ float g_b2f[64];

__device__ __forceinline__ float sigmf(float x) {
    return 1.0f / (1.0f + __expf(-x));
}
__device__ __forceinline__ float geluf(float v) {
    return 0.5f * v * (1.0f + erff(v * 0.70710678118654752f));
}

// ---------------- Gram partials ----------------
__global__ __launch_bounds__(256) void k_gram_part(const float* __restrict__ x)
{
    __shared__ float sx[8][64];
    int chunk = blockIdx.x;
    int base  = chunk * 256;
    int tid = threadIdx.x;
    int ti = tid >> 4, tj = tid & 15;
    float a00=0,a01=0,a02=0,a03=0, a10=0,a11=0,a12=0,a13=0;
    float a20=0,a21=0,a22=0,a23=0, a30=0,a31=0,a32=0,a33=0;

    for (int pp = 0; pp < 256; pp += 8) {
        __syncthreads();
        int idx = tid * 2;
        int pr = idx >> 6, cc = idx & 63;
        float2 v2 = *(const float2*)&x[(size_t)(base + pp + pr)*CC + cc];
        sx[pr][cc] = v2.x; sx[pr][cc+1] = v2.y;
        __syncthreads();
        #pragma unroll
        for (int p = 0; p < 8; p++) {
            float4 xi = *(const float4*)&sx[p][4*ti];
            float4 xj = *(const float4*)&sx[p][4*tj];
            a00 += xi.x*xj.x; a01 += xi.x*xj.y; a02 += xi.x*xj.z; a03 += xi.x*xj.w;
            a10 += xi.y*xj.x; a11 += xi.y*xj.y; a12 += xi.y*xj.z; a13 += xi.y*xj.w;
            a20 += xi.z*xj.x; a21 += xi.z*xj.y; a22 += xi.z*xj.z; a23 += xi.z*xj.w;
            a30 += xi.w*xj.x; a31 += xi.w*xj.y; a32 += xi.w*xj.z; a33 += xi.w*xj.w;
        }
    }
    float* dst = &g_gpart[(size_t)chunk*4096];
    int r = 4*ti, c = 4*tj;
    dst[(r+0)*64+c+0]=a00; dst[(r+0)*64+c+1]=a01; dst[(r+0)*64+c+2]=a02; dst[(r+0)*64+c+3]=a03;
    dst[(r+1)*64+c+0]=a10; dst[(r+1)*64+c+1]=a11; dst[(r+1)*64+c+2]=a12; dst[(r+1)*64+c+3]=a13;
    dst[(r+2)*64+c+0]=a20; dst[(r+2)*64+c+1]=a21; dst[(r+2)*64+c+2]=a22; dst[(r+2)*64+c+3]=a23;
    dst[(r+3)*64+c+0]=a30; dst[(r+3)*64+c+1]=a31; dst[(r+3)*64+c+2]=a32; dst[(r+3)*64+c+3]=a33;
}

// two-stage deterministic reduce: 512 chunks -> 32 partials -> 2 grams
__global__ void k_gram_red1()
{
    int e = blockIdx.x*blockDim.x + threadIdx.x;   // 0 .. 32*4096-1
    if (e >= 32*4096) return;
    int part = e >> 12, i = e & 4095;              // part 0..31 (16 per batch)
    float s = 0.f;
    #pragma unroll
    for (int c = 0; c < 16; c++)
        s += g_gpart[(size_t)(part*16 + c)*4096 + i];
    g_gpart2[e] = s;
}
__global__ void k_gram_red2()
{
    int e = blockIdx.x*blockDim.x + threadIdx.x;   // 0 .. 8191
    if (e >= BN*4096) return;
    int b = e >> 12, i = e & 4095;
    float s = 0.f;
    #pragma unroll
    for (int c = 0; c < 16; c++)
        s += g_gpart2[(size_t)(b*16 + c)*4096 + i];
    g_gram[e] = s;
}

// ---------------- fold W2*W1 and b2f = W2 b1 + b2 ----------------
__global__ __launch_bounds__(256) void k_fold(const float* __restrict__ W1,
                                              const float* __restrict__ b1,
                                              const float* __restrict__ W2,
                                              const float* __restrict__ b2)
{
    __shared__ float sW1[4096];
    __shared__ float sW2[4096];
    int tid = threadIdx.x;
    for (int t = tid; t < 4096; t += 256) { sW1[t] = W1[t]; sW2[t] = W2[t]; }
    __syncthreads();
    for (int t = tid; t < 4096; t += 256) {
        int o = t >> 6, c = t & 63;
        float s = 0.f;
        #pragma unroll 8
        for (int i = 0; i < 64; i++) s += sW2[o*64+i] * sW1[i*64+c];
        g_w2f[t] = s;
    }
    if (tid < 64) {
        float s = b2[tid];
        #pragma unroll 8
        for (int i = 0; i < 64; i++) s += sW2[tid*64+i] * b1[i];
        g_b2f[tid] = s;
    }
}

// ---------------- tiny solve: attn from Gram, fold Wp*A -> g_wfold ----------------
// dynamic smem: sG[4096] sGq[4096] sW[4096] sLog[1024] sNq[64] sNk[64] sPart[256]
__global__ __launch_bounds__(256) void k_small3(const float* __restrict__ Wq,
                                                const float* __restrict__ Wk,
                                                const float* __restrict__ Wp,
                                                const float* __restrict__ rs)
{
    extern __shared__ float dyn[];
    float* sG   = dyn;
    float* sGq  = dyn + 4096;
    float* sW   = dyn + 8192;
    float* sLog = dyn + 12288;
    float* sNq  = dyn + 13312;
    float* sNk  = dyn + 13376;
    float* sPart= dyn + 13440;
    int b = blockIdx.x;
    int tid = threadIdx.x;

    for (int t = tid; t < 4096; t += 256) { sG[t] = g_gram[b*4096 + t]; sW[t] = Wq[t]; }
    __syncthreads();
    // Gq[c][o] = (G Wq^T)[c][o]
    for (int t = tid; t < 4096; t += 256) {
        int c = t >> 6, o = t & 63;
        float s = 0.f;
        #pragma unroll 8
        for (int i = 0; i < 64; i++) s += sG[c*64+i] * sW[o*64+i];
        sGq[t] = s;
    }
    __syncthreads();
    // qq norms (uses sW=Wq, sGq)
    if (tid < 64) {
        int o = tid;
        float qq = 0.f;
        #pragma unroll 8
        for (int c = 0; c < 64; c++) qq += sW[o*64+c] * sGq[c*64+o];
        sNq[o] = fmaxf(sqrtf(fmaxf(qq, 0.f)), 1e-12f);
    }
    __syncthreads();
    // swap W pane to Wk
    for (int t = tid; t < 4096; t += 256) sW[t] = Wk[t];
    __syncthreads();
    // kk partials: 4 threads per o
    {
        int o = tid >> 2, part = tid & 3;
        float kp = 0.f;
        for (int c = part*16; c < part*16 + 16; c++) {
            float gk = 0.f;
            #pragma unroll 8
            for (int i = 0; i < 64; i++) gk += sG[c*64+i] * sW[o*64+i];
            kp += sW[o*64+c] * gk;
        }
        sPart[tid] = kp;
    }
    __syncthreads();
    if (tid < 64) {
        float kk = sPart[4*tid] + sPart[4*tid+1] + sPart[4*tid+2] + sPart[4*tid+3];
        sNk[tid] = fmaxf(sqrtf(fmaxf(kk, 0.f)), 1e-12f);
    }
    __syncthreads();
    // logits (uses sW=Wk, sGq)
    for (int t = tid; t < 1024; t += 256) {
        int h = t >> 8, d = (t >> 4) & 15, e = t & 15;
        int rk = h*16 + d, rq = h*16 + e;
        float s = 0.f;
        #pragma unroll 8
        for (int c = 0; c < 64; c++) s += sW[rk*64+c] * sGq[c*64+rq];
        sLog[t] = s / (sNk[rk] * sNq[rq]) * rs[h];
    }
    __syncthreads();
    if (tid < 64) {
        float* row = &sLog[tid*16];
        float m = row[0];
        for (int e = 1; e < 16; e++) m = fmaxf(m, row[e]);
        float sum = 0.f;
        for (int e = 0; e < 16; e++) { float ev = expf(row[e]-m); row[e] = ev; sum += ev; }
        float inv = 1.f / sum;
        for (int e = 0; e < 16; e++) row[e] *= inv;
    }
    __syncthreads();
    // swap W pane to Wp
    for (int t = tid; t < 4096; t += 256) sW[t] = Wp[t];
    __syncthreads();
    // Wfold = Wp * A (block-diag)
    for (int t = tid; t < 4096; t += 256) {
        int o = t >> 6, j = t & 63, hj = j >> 4, ej = j & 15;
        float s = 0.f;
        #pragma unroll
        for (int d = 0; d < 16; d++)
            s += sW[o*64 + hj*16 + d] * sLog[(hj*16 + d)*16 + ej];
        g_wfold[b*4096 + t] = s;
    }
}

// ---------------- matvec, one W-row per lane ----------------
__global__ __launch_bounds__(256) void k_mv_b(const float* __restrict__ in,
                                              const float* __restrict__ Wg,
                                              const float* __restrict__ bias,
                                              const float* __restrict__ add,
                                              float* __restrict__ out,
                                              int wsel)
{
    __shared__ float4 sx4[2048];              // 32 KB
    float* sx = (float*)sx4;
    int tid = threadIdx.x, lane = tid & 31, wid = tid >> 5;
    int grp = wid >> 2;
    int row = grp*32 + lane;
    const float* W = Wg + (wsel ? (int)(blockIdx.x >> 9) * 4096 : 0);

    for (int t = tid; t < 4096; t += 256) sx[(t >> 6)*68 + (t & 63)] = W[t];
    __syncthreads();
    float w[64];
    #pragma unroll
    for (int k = 0; k < 16; k++) {
        float4 a = *(const float4*)&sx[row*68 + 4*k];
        w[4*k+0]=a.x; w[4*k+1]=a.y; w[4*k+2]=a.z; w[4*k+3]=a.w;
    }
    float bb = bias ? bias[row] : 0.f;
    __syncthreads();

    size_t pbase = (size_t)blockIdx.x * 128;
    const float4* in4 = (const float4*)in + pbase*16;
    #pragma unroll
    for (int j = 0; j < 8; j++) sx4[tid + 256*j] = in4[tid + 256*j];
    __syncthreads();

    int pw = (wid & 3) * 32;
    #pragma unroll 2
    for (int q = 0; q < 8; q++) {
        int p0 = pw + q*4;
        float a0 = bb, a1 = bb, a2 = bb, a3 = bb;
        #pragma unroll
        for (int k4 = 0; k4 < 16; k4++) {
            float4 x0 = *(const float4*)&sx[(p0+0)*64 + 4*k4];
            float4 x1 = *(const float4*)&sx[(p0+1)*64 + 4*k4];
            float4 x2 = *(const float4*)&sx[(p0+2)*64 + 4*k4];
            float4 x3 = *(const float4*)&sx[(p0+3)*64 + 4*k4];
            a0 = fmaf(w[4*k4+0], x0.x, a0); a0 = fmaf(w[4*k4+1], x0.y, a0);
            a0 = fmaf(w[4*k4+2], x0.z, a0); a0 = fmaf(w[4*k4+3], x0.w, a0);
            a1 = fmaf(w[4*k4+0], x1.x, a1); a1 = fmaf(w[4*k4+1], x1.y, a1);
            a1 = fmaf(w[4*k4+2], x1.z, a1); a1 = fmaf(w[4*k4+3], x1.w, a1);
            a2 = fmaf(w[4*k4+0], x2.x, a2); a2 = fmaf(w[4*k4+1], x2.y, a2);
            a2 = fmaf(w[4*k4+2], x2.z, a2); a2 = fmaf(w[4*k4+3], x2.w, a2);
            a3 = fmaf(w[4*k4+0], x3.x, a3); a3 = fmaf(w[4*k4+1], x3.y, a3);
            a3 = fmaf(w[4*k4+2], x3.z, a3); a3 = fmaf(w[4*k4+3], x3.w, a3);
        }
        size_t o0 = (pbase + p0)*64 + row;
        if (add) {
            a0 += add[o0]; a1 += add[o0+64]; a2 += add[o0+128]; a3 += add[o0+192];
        }
        out[o0]     = a0;
        out[o0+64]  = a1;
        out[o0+128] = a2;
        out[o0+192] = a3;
    }
}

// ---------------- dwconv, 4-pixel strips, channel-group fast ----------------
__global__ __launch_bounds__(256) void k_pe1_s(const float* __restrict__ x,
                                               const float* __restrict__ w)
{
    __shared__ float sw[9*CC];
    for (int t = threadIdx.x; t < 9*CC; t += 256) { int c = t/9, k = t%9; sw[k*CC+c] = w[t]; }
    __syncthreads();
    int g = threadIdx.x & 15, strip = threadIdx.x >> 4;
    int pbase = blockIdx.x*64 + strip*4;
    int b = pbase >> 16, s = pbase & 65535, y = s >> 8, x0 = s & 255;
    const float4* x4 = (const float4*)x;
    const float4* sw4 = (const float4*)sw;
    float4 acc[4];
    #pragma unroll
    for (int p = 0; p < 4; p++) acc[p] = make_float4(0.f,0.f,0.f,0.f);
    size_t bb = (size_t)(b << 16);
    #pragma unroll
    for (int ky = 0; ky < 3; ky++) {
        int yy = y + ky - 1; if (yy < 0 || yy >= HH) continue;
        #pragma unroll
        for (int c = -1; c <= 4; c++) {
            int xc = x0 + c; if (xc < 0 || xc >= WWD) continue;
            float4 v = x4[(bb + (yy<<8) + xc)*16 + g];
            #pragma unroll
            for (int p = 0; p < 4; p++) {
                int kx = c - p + 1; if (kx < 0 || kx > 2) continue;
                float4 wv = sw4[(ky*3+kx)*16 + g];
                acc[p].x = fmaf(wv.x, v.x, acc[p].x); acc[p].y = fmaf(wv.y, v.y, acc[p].y);
                acc[p].z = fmaf(wv.z, v.z, acc[p].z); acc[p].w = fmaf(wv.w, v.w, acc[p].w);
            }
        }
    }
    float4* t14 = (float4*)g_t1;
    #pragma unroll
    for (int p = 0; p < 4; p++) {
        float4 r;
        r.x = geluf(acc[p].x); r.y = geluf(acc[p].y);
        r.z = geluf(acc[p].z); r.w = geluf(acc[p].w);
        t14[(size_t)(pbase+p)*16 + g] = r;
    }
}

__global__ __launch_bounds__(256) void k_pe2_s(const float* __restrict__ w)
{
    __shared__ float sw[9*CC];
    for (int t = threadIdx.x; t < 9*CC; t += 256) { int c = t/9, k = t%9; sw[k*CC+c] = w[t]; }
    __syncthreads();
    int g = threadIdx.x & 15, strip = threadIdx.x >> 4;
    int pbase = blockIdx.x*64 + strip*4;
    int b = pbase >> 16, s = pbase & 65535, y = s >> 8, x0 = s & 255;
    const float4* t14 = (const float4*)g_t1;
    const float4* sw4 = (const float4*)sw;
    float4 acc[4];
    #pragma unroll
    for (int p = 0; p < 4; p++) acc[p] = make_float4(0.f,0.f,0.f,0.f);
    size_t bb = (size_t)(b << 16);
    #pragma unroll
    for (int ky = 0; ky < 3; ky++) {
        int yy = y + ky - 1; if (yy < 0 || yy >= HH) continue;
        #pragma unroll
        for (int c = -1; c <= 4; c++) {
            int xc = x0 + c; if (xc < 0 || xc >= WWD) continue;
            float4 v = t14[(bb + (yy<<8) + xc)*16 + g];
            #pragma unroll
            for (int p = 0; p < 4; p++) {
                int kx = c - p + 1; if (kx < 0 || kx > 2) continue;
                float4 wv = sw4[(ky*3+kx)*16 + g];
                acc[p].x = fmaf(wv.x, v.x, acc[p].x); acc[p].y = fmaf(wv.y, v.y, acc[p].y);
                acc[p].z = fmaf(wv.z, v.z, acc[p].z); acc[p].w = fmaf(wv.w, v.w, acc[p].w);
            }
        }
    }
    float4* t24 = (float4*)g_t2;
    #pragma unroll
    for (int p = 0; p < 4; p++) t24[(size_t)(pbase+p)*16 + g] = acc[p];
}

__global__ __launch_bounds__(256) void k_ma_s(const float* __restrict__ dw,
                                              const float* __restrict__ dwb)
{
    __shared__ float sdw[25*CC];
    __shared__ float sdb[CC];
    for (int t = threadIdx.x; t < 25*CC; t += 256) { int c = t/25, k = t%25; sdw[k*CC+c] = dw[t]; }
    for (int t = threadIdx.x; t < CC; t += 256) sdb[t] = dwb[t];
    __syncthreads();
    int g = threadIdx.x & 15, strip = threadIdx.x >> 4;
    int pbase = blockIdx.x*64 + strip*4;
    int b = pbase >> 16, s = pbase & 65535, y = s >> 8, x0 = s & 255;
    const float4* m24 = (const float4*)g_m2;
    const float4* sdw4 = (const float4*)sdw;
    float4 bias4 = ((const float4*)sdb)[g];
    float4 acc[4];
    #pragma unroll
    for (int p = 0; p < 4; p++) acc[p] = bias4;
    size_t bb = (size_t)(b << 16);
    #pragma unroll
    for (int ky = 0; ky < 5; ky++) {
        int yy = y + ky - 2; if (yy < 0 || yy >= HH) continue;
        #pragma unroll
        for (int c = -2; c <= 5; c++) {
            int xc = x0 + c; if (xc < 0 || xc >= WWD) continue;
            float4 v = m24[(bb + (yy<<8) + xc)*16 + g];
            #pragma unroll
            for (int p = 0; p < 4; p++) {
                int kx = c - p + 2; if (kx < 0 || kx > 4) continue;
                float4 wv = sdw4[(ky*5+kx)*16 + g];
                acc[p].x = fmaf(wv.x, v.x, acc[p].x); acc[p].y = fmaf(wv.y, v.y, acc[p].y);
                acc[p].z = fmaf(wv.z, v.z, acc[p].z); acc[p].w = fmaf(wv.w, v.w, acc[p].w);
            }
        }
    }
    const float4* m14 = (const float4*)g_m1;
    const float4* v4  = (const float4*)g_v;
    float4* vm4 = (float4*)g_vm;
    #pragma unroll
    for (int p = 0; p < 4; p++) {
        size_t idx = (size_t)(pbase+p)*16 + g;
        float4 m1v = m14[idx], vv = v4[idx];
        float4 r;
        r.x = vv.x * (m1v.x * (1.f + sigmf(acc[p].x)));
        r.y = vv.y * (m1v.y * (1.f + sigmf(acc[p].y)));
        r.z = vv.z * (m1v.z * (1.f + sigmf(acc[p].z)));
        r.w = vv.w * (m1v.w * (1.f + sigmf(acc[p].w)));
        vm4[idx] = r;
    }
}

// ---------------- launcher ----------------
extern "C" void kernel_launch(void* const* d_in, const int* in_sizes, int n_in,
                              void* d_out, int out_size)
{
    const float* x_in   = (const float*)d_in[0];
    const float* mask   = (const float*)d_in[1];
    const float* Wq     = (const float*)d_in[2];
    const float* Wk     = (const float*)d_in[3];
    const float* Wv     = (const float*)d_in[4];
    const float* rescale= (const float*)d_in[5];
    const float* Wp     = (const float*)d_in[6];
    const float* bp     = (const float*)d_in[7];
    const float* mm_w1  = (const float*)d_in[8];
    const float* mm_b1  = (const float*)d_in[9];
    const float* mm_w2  = (const float*)d_in[10];
    const float* mm_b2  = (const float*)d_in[11];
    const float* mm_dw  = (const float*)d_in[12];
    const float* mm_dwb = (const float*)d_in[13];
    const float* pe_w1  = (const float*)d_in[14];
    const float* pe_w2  = (const float*)d_in[15];
    float* out = (float*)d_out;

    float *pm1, *pm2, *pv, *pvm, *pt2, *pwf, *pw2f, *pb2f;
    cudaGetSymbolAddress((void**)&pm1,  g_m1);
    cudaGetSymbolAddress((void**)&pm2,  g_m2);
    cudaGetSymbolAddress((void**)&pv,   g_v);
    cudaGetSymbolAddress((void**)&pvm,  g_vm);
    cudaGetSymbolAddress((void**)&pt2,  g_t2);
    cudaGetSymbolAddress((void**)&pwf,  g_wfold);
    cudaGetSymbolAddress((void**)&pw2f, g_w2f);
    cudaGetSymbolAddress((void**)&pb2f, g_b2f);

    static int smem_set = 0;
    const int SM3_BYTES = (4096*3 + 1024 + 64 + 64 + 256) * 4;  // 54.8 KB
    if (!smem_set) {
        cudaFuncSetAttribute(k_small3, cudaFuncAttributeMaxDynamicSharedMemorySize, SM3_BYTES);
        smem_set = 1;
    }

    // tiny folds + Gram chain
    k_fold<<<1, 256>>>(mm_w1, mm_b1, mm_w2, mm_b2);
    k_gram_part<<<NCHUNK, 256>>>(x_in);
    k_gram_red1<<<(32*4096)/256, 256>>>();
    k_gram_red2<<<(BN*4096)/256, 256>>>();
    k_small3<<<BN, 256, SM3_BYTES>>>(Wq, Wk, Wp, rescale);

    // per-pixel 64x64 matvecs
    k_mv_b<<<NPIX/128, 256>>>(mask, mm_w1, mm_b1, nullptr, pm1, 0);
    k_mv_b<<<NPIX/128, 256>>>(mask, pw2f, pb2f, nullptr, pm2, 0);
    k_mv_b<<<NPIX/128, 256>>>(x_in, Wv, nullptr, nullptr, pv, 0);

    // spatial kernels (4-pixel strips)
    k_pe1_s<<<NPIX/64, 256>>>(x_in, pe_w1);
    k_pe2_s<<<NPIX/64, 256>>>(pe_w2);
    k_ma_s <<<NPIX/64, 256>>>(mm_dw, mm_dwb);

    // final: out = Wfold_b * vm + bp + t2
    k_mv_b<<<NPIX/128, 256>>>(pvm, pwf, bp, pt2, out, 1);
}